// round 7
// baseline (speedup 1.0000x reference)
#include <cuda_runtime.h>
#include <cuda_fp16.h>
#include <cstdint>

#define Nn 8192
#define Mm 128
#define EPSf 1e-4f
#define LDA 136   // fp16 elems per smem tile row (128 + 8 pad)
#define LDL 68    // float words per label smem row (64 + 4 pad)

// ---------------- device scratch (allocation-free) ----------------
static __device__ __half g_A16[(size_t)Nn * Mm];  // out2 fp16
static __device__ __half g_B16[(size_t)Nn * Mm];  // out1 fp16
static __device__ float  g_Z[Nn];
static __device__ float  g_W[Nn];
static __device__ float  g_rZ[Nn];
static __device__ float  g_rW[Nn];
static __device__ double g_loss;

__device__ __forceinline__ uint32_t smem_u32(const void* p) {
    uint32_t a;
    asm("{ .reg .u64 t; cvta.to.shared.u64 t, %1; cvt.u32.u64 %0, t; }" : "=r"(a) : "l"(p));
    return a;
}
__device__ __forceinline__ void ldmx4(uint32_t* r, uint32_t addr) {
    asm volatile("ldmatrix.sync.aligned.m8n8.x4.shared.b16 {%0,%1,%2,%3}, [%4];"
                 : "=r"(r[0]), "=r"(r[1]), "=r"(r[2]), "=r"(r[3]) : "r"(addr));
}
__device__ __forceinline__ void mma16816(float* c, const uint32_t* a, uint32_t b0, uint32_t b1) {
    asm volatile(
        "mma.sync.aligned.m16n8k16.row.col.f32.f16.f16.f32 "
        "{%0,%1,%2,%3}, {%4,%5,%6,%7}, {%8,%9}, {%0,%1,%2,%3};"
        : "+f"(c[0]), "+f"(c[1]), "+f"(c[2]), "+f"(c[3])
        : "r"(a[0]), "r"(a[1]), "r"(a[2]), "r"(a[3]), "r"(b0), "r"(b1));
}
#define CP_ASYNC16(dst, src) \
    asm volatile("cp.async.cg.shared.global [%0], [%1], 16;" :: "r"(dst), "l"(src))
#define CP_COMMIT() asm volatile("cp.async.commit_group;")
#define CP_WAIT0()  asm volatile("cp.async.wait_group 0;")

__global__ void prep_kernel(const float* __restrict__ out1, const float* __restrict__ out2) {
    int t = blockIdx.x * blockDim.x + threadIdx.x;
    if (t < Nn * Mm / 4) {
        float4 a = *(const float4*)&out2[(size_t)t * 4];
        float4 b = *(const float4*)&out1[(size_t)t * 4];
        __half2 a0 = __float22half2_rn(make_float2(a.x, a.y));
        __half2 a1 = __float22half2_rn(make_float2(a.z, a.w));
        __half2 b0 = __float22half2_rn(make_float2(b.x, b.y));
        __half2 b1 = __float22half2_rn(make_float2(b.z, b.w));
        *(uint2*)&g_A16[(size_t)t * 4] = make_uint2(*(uint32_t*)&a0, *(uint32_t*)&a1);
        *(uint2*)&g_B16[(size_t)t * 4] = make_uint2(*(uint32_t*)&b0, *(uint32_t*)&b1);
    }
    if (t < Nn) { g_Z[t] = 0.0f; g_W[t] = 0.0f; }
    if (t == 0) g_loss = 0.0;
}

#define A_ELEMS (128 * LDA)           // halfs
#define B_ELEMS (64 * LDA)            // halfs
#define AB_BYTES ((A_ELEMS + B_ELEMS) * 2)           // 52224
#define L_BYTES  (128 * LDL * 4)                     // 34816
#define SMEM_P1  AB_BYTES
#define SMEM_P2  (AB_BYTES + L_BYTES)                // 87040

// tile loader: A 128 rows, B 64 rows of fp16 (128/row) -> padded smem
__device__ __forceinline__ void load_tiles(__half* At, __half* Bt, int i0, int j0, int tid) {
    #pragma unroll 8
    for (int t = tid; t < 2048; t += 256) {
        int row = t >> 4, q = (t & 15) * 8;
        *(uint4*)&At[row * LDA + q] = *(const uint4*)&g_A16[(size_t)(i0 + row) * Mm + q];
    }
    #pragma unroll 4
    for (int t = tid; t < 1024; t += 256) {
        int row = t >> 4, q = (t & 15) * 8;
        *(uint4*)&Bt[row * LDA + q] = *(const uint4*)&g_B16[(size_t)(j0 + row) * Mm + q];
    }
}

// MMA body for warp tile 32(m) x 32(n): c[2][4][4]
__device__ __forceinline__ void mma_tile(const __half* At, const __half* Bt,
                                         int m0w, int n0w, int lane, float c[2][4][4]) {
    const int aro = (lane & 7) + ((lane >> 3) & 1) * 8;
    const int ako = ((lane >> 4) & 1) * 8;
    const int bro = (lane & 7) + ((lane >> 4) & 1) * 8;
    const int bko = ((lane >> 3) & 1) * 8;

    const uint32_t sA = smem_u32(At), sB = smem_u32(Bt);
    const uint32_t aoff = (uint32_t)(((m0w + aro) * LDA + ako) * 2);
    uint32_t boff[2];
    #pragma unroll
    for (int p = 0; p < 2; p++)
        boff[p] = (uint32_t)(((n0w + p * 16 + bro) * LDA + bko) * 2);

    #pragma unroll
    for (int kk = 0; kk < 8; kk++) {
        const uint32_t kb = (uint32_t)(kk * 32);
        uint32_t av[2][4], bv[2][4];
        #pragma unroll
        for (int mt = 0; mt < 2; mt++)
            ldmx4(av[mt], sA + aoff + (uint32_t)(mt * 16 * LDA * 2) + kb);
        #pragma unroll
        for (int p = 0; p < 2; p++)
            ldmx4(bv[p], sB + boff[p] + kb);
        #pragma unroll
        for (int mt = 0; mt < 2; mt++)
            #pragma unroll
            for (int nt = 0; nt < 4; nt++) {
                const int p = nt >> 1, r = (nt & 1) * 2;
                mma16816(c[mt][nt], av[mt], bv[p][r], bv[p][r + 1]);
            }
    }
}

// ---------------- Pass 1: GEMM -> exp -> row/col sums ----------------
__global__ __launch_bounds__(256, 3) void pass1_sums() {
    extern __shared__ char sm[];
    __half* At = (__half*)sm;
    __half* Bt = At + A_ELEMS;

    const int tid = threadIdx.x, wid = tid >> 5, lane = tid & 31;
    const int i0 = blockIdx.y * 128, j0 = blockIdx.x * 64;
    const int m0w = (wid & 3) * 32, n0w = (wid >> 2) * 32;

    load_tiles(At, Bt, i0, j0, tid);
    __syncthreads();

    float c[2][4][4] = {};
    mma_tile(At, Bt, m0w, n0w, lane, c);

    #pragma unroll
    for (int mt = 0; mt < 2; mt++)
        #pragma unroll
        for (int nt = 0; nt < 4; nt++)
            #pragma unroll
            for (int q = 0; q < 4; q++) c[mt][nt][q] = __expf(c[mt][nt][q]);

    // row sums
    #pragma unroll
    for (int mt = 0; mt < 2; mt++) {
        float r0 = 0.f, r1 = 0.f;
        #pragma unroll
        for (int nt = 0; nt < 4; nt++) {
            r0 += c[mt][nt][0] + c[mt][nt][1];
            r1 += c[mt][nt][2] + c[mt][nt][3];
        }
        r0 += __shfl_xor_sync(0xFFFFFFFF, r0, 1);
        r0 += __shfl_xor_sync(0xFFFFFFFF, r0, 2);
        r1 += __shfl_xor_sync(0xFFFFFFFF, r1, 1);
        r1 += __shfl_xor_sync(0xFFFFFFFF, r1, 2);
        if ((lane & 3) == 0) {
            atomicAdd(&g_Z[i0 + m0w + mt * 16 + (lane >> 2)], r0);
            atomicAdd(&g_Z[i0 + m0w + mt * 16 + 8 + (lane >> 2)], r1);
        }
    }
    // col sums
    #pragma unroll
    for (int nt = 0; nt < 4; nt++) {
        float v0 = c[0][nt][0] + c[0][nt][2] + c[1][nt][0] + c[1][nt][2];
        float v1 = c[0][nt][1] + c[0][nt][3] + c[1][nt][1] + c[1][nt][3];
        v0 += __shfl_xor_sync(0xFFFFFFFF, v0, 4);
        v0 += __shfl_xor_sync(0xFFFFFFFF, v0, 8);
        v0 += __shfl_xor_sync(0xFFFFFFFF, v0, 16);
        v1 += __shfl_xor_sync(0xFFFFFFFF, v1, 4);
        v1 += __shfl_xor_sync(0xFFFFFFFF, v1, 8);
        v1 += __shfl_xor_sync(0xFFFFFFFF, v1, 16);
        if (lane < 4) {
            int col = j0 + n0w + nt * 8 + lane * 2;
            atomicAdd(&g_W[col], v0);
            atomicAdd(&g_W[col + 1], v1);
        }
    }
}

__global__ void recip_kernel() {
    int i = blockIdx.x * blockDim.x + threadIdx.x;
    if (i < Nn) { g_rZ[i] = 1.0f / g_Z[i]; g_rW[i] = 1.0f / g_W[i]; }
}

// ---------------- Pass 2: cp.async label prefetch + GEMM + fused loss ----------------
__global__ __launch_bounds__(256, 2) void pass2_fused(const float* __restrict__ label) {
    extern __shared__ char sm[];
    __half* At = (__half*)sm;
    __half* Bt = At + A_ELEMS;
    float*  Lt = (float*)(sm + AB_BYTES);

    const int tid = threadIdx.x, wid = tid >> 5, lane = tid & 31;
    const int i0 = blockIdx.y * 128, j0 = blockIdx.x * 64;
    const int m0w = (wid & 3) * 32, n0w = (wid >> 2) * 32;

    // prefetch label tile (128 x 64 f32) via cp.async — overlaps with MMA
    const uint32_t ltb = smem_u32(Lt);
    #pragma unroll 8
    for (int t = tid; t < 2048; t += 256) {
        int row = t >> 4, cx = (t & 15) * 4;
        CP_ASYNC16(ltb + (uint32_t)((row * LDL + cx) * 4),
                   &label[(size_t)(i0 + row) * Nn + j0 + cx]);
    }
    CP_COMMIT();

    load_tiles(At, Bt, i0, j0, tid);
    __syncthreads();

    float c[2][4][4] = {};
    mma_tile(At, Bt, m0w, n0w, lane, c);

    CP_WAIT0();
    __syncthreads();

    float acc = 0.f;
    #pragma unroll
    for (int mt = 0; mt < 2; mt++) {
        const int rl = m0w + mt * 16 + (lane >> 2);
        const float rZ0 = g_rZ[i0 + rl], rZ8 = g_rZ[i0 + rl + 8];
        #pragma unroll
        for (int nt = 0; nt < 4; nt++) {
            const int lcol = n0w + nt * 8 + (lane & 3) * 2;
            const float rw0 = g_rW[j0 + lcol], rw1 = g_rW[j0 + lcol + 1];
            float2 l0 = *(const float2*)&Lt[rl * LDL + lcol];
            float2 l1 = *(const float2*)&Lt[(rl + 8) * LDL + lcol];

            float e0 = __expf(c[mt][nt][0]);
            float e1 = __expf(c[mt][nt][1]);
            float e2 = __expf(c[mt][nt][2]);
            float e3 = __expf(c[mt][nt][3]);

            acc += l0.x * __logf(fmaf(e0, rZ0, EPSf) * fmaf(e0, rw0, EPSf));
            acc += l0.y * __logf(fmaf(e1, rZ0, EPSf) * fmaf(e1, rw1, EPSf));
            acc += l1.x * __logf(fmaf(e2, rZ8, EPSf) * fmaf(e2, rw0, EPSf));
            acc += l1.y * __logf(fmaf(e3, rZ8, EPSf) * fmaf(e3, rw1, EPSf));
        }
    }

    __syncthreads();
    float* red = (float*)sm;
    acc += __shfl_xor_sync(0xFFFFFFFF, acc, 16);
    acc += __shfl_xor_sync(0xFFFFFFFF, acc, 8);
    acc += __shfl_xor_sync(0xFFFFFFFF, acc, 4);
    acc += __shfl_xor_sync(0xFFFFFFFF, acc, 2);
    acc += __shfl_xor_sync(0xFFFFFFFF, acc, 1);
    if (lane == 0) red[wid] = acc;
    __syncthreads();
    if (tid == 0) {
        float s = 0.f;
        #pragma unroll
        for (int w = 0; w < 8; w++) s += red[w];
        atomicAdd(&g_loss, -(double)s);
    }
}

__global__ void final_kernel(float* out) { out[0] = (float)g_loss; }

extern "C" void kernel_launch(void* const* d_in, const int* in_sizes, int n_in,
                              void* d_out, int out_size) {
    const float* out1  = (const float*)d_in[0];
    const float* out2  = (const float*)d_in[1];
    const float* label = (const float*)d_in[2];

    cudaFuncSetAttribute(pass1_sums, cudaFuncAttributeMaxDynamicSharedMemorySize, SMEM_P1);
    cudaFuncSetAttribute(pass2_fused, cudaFuncAttributeMaxDynamicSharedMemorySize, SMEM_P2);

    prep_kernel<<<(Nn * Mm / 4 + 255) / 256, 256>>>(out1, out2);
    dim3 grid(Nn / 64, Nn / 128);
    pass1_sums<<<grid, 256, SMEM_P1>>>();
    recip_kernel<<<32, 256>>>();
    pass2_fused<<<grid, 256, SMEM_P2>>>(label);
    final_kernel<<<1, 1>>>((float*)d_out);
}